// round 12
// baseline (speedup 1.0000x reference)
#include <cuda_runtime.h>

// ReNet layer, R11: 4 seq-groups(M=8) x 4 hid-quarters. Lane = (hid16, gatepair)
// -> acc is ONE ull per seq; weight load = conflict-free LDS.64/lane; crossbar
// = FMA budget (64 cyc/k/SM). Double-buffered 4-k chunks fit in 128 regs.
// Gate halves merged with one 64-bit shfl.down(1). 2 group barriers/step.

#define HIDN 64
#define NGC  256
#define BN   16
#define SJ   128
#define NSEQ 32
#define NTHR 512

typedef unsigned long long ull;

__device__ float g_v[BN * SJ * SJ * 2 * HIDN];   // vertical output [B][J][I][128]

__device__ __forceinline__ ull pack2(float lo, float hi) {
    ull r; asm("mov.b64 %0, {%1, %2};" : "=l"(r) : "f"(lo), "f"(hi)); return r;
}
__device__ __forceinline__ void unpack2(ull v, float& lo, float& hi) {
    asm("mov.b64 {%0, %1}, %2;" : "=f"(lo), "=f"(hi) : "l"(v));
}
__device__ __forceinline__ void ffma2(ull& d, ull a, ull b) {
    asm("fma.rn.f32x2 %0, %1, %2, %0;" : "+l"(d) : "l"(a), "l"(b));
}
__device__ __forceinline__ float sigf(float x)   { return 1.0f / (1.0f + __expf(-x)); }
__device__ __forceinline__ float mytanh(float x) { return 1.0f - 2.0f / (__expf(2.0f * x) + 1.0f); }
__device__ __forceinline__ void bar_grp(int sg) {
    asm volatile("bar.sync %0, 128;" :: "r"(sg + 1) : "memory");
}

template <int DIN>
__global__ void __launch_bounds__(NTHR, 1)
renet_pass(const float* __restrict__ W0, const float* __restrict__ U0, const float* __restrict__ b0,
           const float* __restrict__ W1, const float* __restrict__ U1, const float* __restrict__ b1,
           const float* __restrict__ src, float* __restrict__ dst)
{
    constexpr int K  = DIN + HIDN;
    constexpr int KP = (K + 7) & ~7;          // padded (zero weights / zero x pad)
    extern __shared__ float sm[];
    float* sWU = sm;                   // [KP][NGC]  combined W;U, quarter/gate layout
    float* sXH = sm + KP * NGC;        // [NSEQ][KP] per-seq (x_t ++ h ++ pad)
    float* sB  = sXH + NSEQ * KP;      // [NGC]

    const int dir  = blockIdx.x >> 6;
    const int s0   = (blockIdx.x & 63) * NSEQ;
    const int tid  = threadIdx.x;
    const int lane = tid & 31;
    const int wid  = tid >> 5;
    const int hq   = wid & 3;                 // hid quarter (16 hid)
    const int sg   = wid >> 2;                // seq group: 8 seqs, 0..3
    const int gtid = tid & 127;               // thread id within group
    const int hid16 = lane >> 1;              // hid within quarter
    const int gp    = lane & 1;               // gate pair: 0 -> (i,f), 1 -> (g,o)
    const int hid   = hq * 16 + hid16;

    const float* W  = dir ? W1 : W0;
    const float* U  = dir ? U1 : U0;
    const float* bb = dir ? b1 : b0;

    // weight layout: sWU[k][ (h>>4)*64 + (h&15)*4 + g ] = orig[k][g*64 + h]
    // -> lane (hid16,gp) loads ull at hq*64 + hid16*4 + gp*2: 8B/lane contiguous
    for (int idx = tid; idx < KP * NGC; idx += NTHR) {
        int k = idx >> 8, c = idx & 255;
        int g = c >> 6, h = c & 63;
        int pc = (h >> 4) * 64 + (h & 15) * 4 + g;
        float v = (k < DIN) ? W[k * NGC + c]
                 : (k < K)  ? U[(k - DIN) * NGC + c] : 0.0f;
        sWU[k * NGC + pc] = v;
    }
    for (int idx = tid; idx < NGC; idx += NTHR) sB[idx] = bb[idx];
    for (int idx = tid; idx < NSEQ * (KP - DIN); idx += NTHR) {
        int s = idx / (KP - DIN), o = idx % (KP - DIN);
        sXH[s * KP + DIN + o] = 0.0f;          // h_0 = 0 and k-pad = 0
    }
    __syncthreads();

    // bias for this lane's gate pair
    const ull binit = gp ? pack2(sB[2 * HIDN + hid], sB[3 * HIDN + hid])
                         : pack2(sB[0 * HIDN + hid], sB[1 * HIDN + hid]);

    float cst[8];
#pragma unroll
    for (int p = 0; p < 8; p++) cst[p] = 0.0f;

    // ---- group-local x staging for step t into rows [8sg, 8sg+8), 128 thr
    auto stage_x = [&](int t) {
        if (DIN == 12) {
            const int jin = dir ? (SJ - 1 - t) : t;
            if (gtid < 8 * 12) {
                int sl = gtid / 12, d = gtid - sl * 12;
                int q = s0 + sg * 8 + sl;
                int b = q >> 7, i = q & 127;
                int pr = d / 6, rm = d - pr * 6;
                int pc = rm / 3, ch = rm - pc * 3;
                sXH[(sg * 8 + sl) * KP + d] =
                    src[((b * 256 + (2 * jin + pr)) * 256 + (2 * i + pc)) * 3 + ch];
            }
        } else {
            const int iin = dir ? (SJ - 1 - t) : t;
#pragma unroll
            for (int r = 0; r < 2; r++) {
                int idx = gtid + 128 * r;      // 256 = 8 seq * 32 float4
                int sl = idx >> 5, f4 = idx & 31;
                int q = s0 + sg * 8 + sl;
                int b = q >> 7, j = q & 127;
                float4 v4 = *(const float4*)
                    &src[((size_t)((b * 128 + j) * 128 + iin)) * 128 + f4 * 4];
                *(float4*)&sXH[(sg * 8 + sl) * KP + f4 * 4] = v4;
            }
        }
    };

    stage_x(0);

    const float* xbase = sXH + (sg * 8) * KP;
    const float* wbase = sWU + hq * 64 + hid16 * 4 + gp * 2;

    for (int t = 0; t < SJ; t++) {
        bar_grp(sg);                           // A: x_t staged, h_{t-1} visible

        ull acc[8];
#pragma unroll
        for (int m = 0; m < 8; m++) acc[m] = binit;

        float4 xA[8], xB[8];
        ull wA[4], wB[4];

        auto loadx = [&](float4* xq, int k) {
#pragma unroll
            for (int m = 0; m < 8; m++) xq[m] = *(const float4*)&xbase[m * KP + k];
        };
        auto loadw = [&](ull* wq, int k) {
#pragma unroll
            for (int kk = 0; kk < 4; kk++)
                wq[kk] = *(const ull*)(wbase + (k + kk) * NGC);
        };
        auto chunk = [&](const float4* xq, const ull* wq) {
#pragma unroll
            for (int kk = 0; kk < 4; kk++) {
#pragma unroll
                for (int m = 0; m < 8; m++) {
                    float a = ((const float*)&xq[m])[kk];
                    ffma2(acc[m], pack2(a, a), wq[kk]);
                }
            }
        };

        loadx(xA, 0); loadw(wA, 0);
#pragma unroll 1
        for (int k = 0; k < KP; k += 8) {
            loadx(xB, k + 4); loadw(wB, k + 4);
            chunk(xA, wA);
            if (k + 8 < KP) { loadx(xA, k + 8); loadw(wA, k + 8); }
            chunk(xB, wB);
        }

        bar_grp(sg);                           // B: group's reads of sXH done

        // ---- merge gate pairs, elementwise on gp==0 lanes
#pragma unroll
        for (int m = 0; m < 8; m++) {
            ull zgo = __shfl_down_sync(0xffffffffu, acc[m], 1);
            if (gp == 0) {
                float zi, zf, zg, zo;
                unpack2(acc[m], zi, zf);
                unpack2(zgo, zg, zo);
                float c = sigf(zf) * cst[m] + sigf(zi) * mytanh(zg);
                cst[m] = c;
                float hv = sigf(zo) * mytanh(c);

                int s = sg * 8 + m;
                sXH[s * KP + DIN + hid] = hv;

                int q = s0 + s;
                int b = q >> 7, w = q & 127;
                int row = (DIN == 12) ? t : w;
                int col = (DIN == 12) ? w : t;
                dst[((size_t)((b * 128 + row) * 128 + col)) * 128 + dir * 64 + hid] = hv;
            }
        }

        if (t + 1 < SJ) stage_x(t + 1);        // x region disjoint from h region
    }
}

extern "C" void kernel_launch(void* const* d_in, const int* in_sizes, int n_in,
                              void* d_out, int out_size)
{
    const float* inputs = (const float*)d_in[0];
    const float* W_ud = (const float*)d_in[1];
    const float* U_ud = (const float*)d_in[2];
    const float* b_ud = (const float*)d_in[3];
    const float* W_du = (const float*)d_in[4];
    const float* U_du = (const float*)d_in[5];
    const float* b_du = (const float*)d_in[6];
    const float* W_lr = (const float*)d_in[7];
    const float* U_lr = (const float*)d_in[8];
    const float* b_lr = (const float*)d_in[9];
    const float* W_rl = (const float*)d_in[10];
    const float* U_rl = (const float*)d_in[11];
    const float* b_rl = (const float*)d_in[12];

    float* vbuf = nullptr;
    cudaGetSymbolAddress((void**)&vbuf, g_v);

    constexpr int KP1 = 80;    // (12+64) padded to 8
    constexpr int KP2 = 192;   // 128+64
    size_t smem1 = (size_t)(KP1 * NGC + NSEQ * KP1 + NGC) * sizeof(float);  //  93,184 B
    size_t smem2 = (size_t)(KP2 * NGC + NSEQ * KP2 + NGC) * sizeof(float);  // 222,208 B

    cudaFuncSetAttribute(renet_pass<12>,  cudaFuncAttributeMaxDynamicSharedMemorySize, (int)smem1);
    cudaFuncSetAttribute(renet_pass<128>, cudaFuncAttributeMaxDynamicSharedMemorySize, (int)smem2);

    renet_pass<12><<<128, NTHR, smem1>>>(W_ud, U_ud, b_ud, W_du, U_du, b_du,
                                         inputs, vbuf);
    renet_pass<128><<<128, NTHR, smem2>>>(W_lr, U_lr, b_lr, W_rl, U_rl, b_rl,
                                          vbuf, (float*)d_out);
}